// round 14
// baseline (speedup 1.0000x reference)
#include <cuda_runtime.h>
#include <cuda_bf16.h>

// Problem constants
#define F 26
#define B 16384
#define V 100000
#define D 32
#define H 13

#define TPB   256
#define ITEMS 8
// total float4s = B*F*(D/4) = 3,407,872 = 1664 blocks * 256 threads * 8 items
#define GRID  1664

// Fused kernel (R5 winner config; ONLY change: plain write-back stores so the
// output stays L2-resident across graph replays instead of streaming to DRAM):
//   prologue (warp 0): scale[f] = sigmoid(w2 @ relu(w1 @ mean_d(emb[f, x[f,B-1], :])))
//     (reference uses ONLY the last batch row for the gate: scale = gate[-1])
//   main: out[b, f*D+d] = tables[f][x[f,b]][d] * scale[f]
// One thread per 8 output float4s, item stride = TPB. Since TPB % 8 == 0, the
// float4-within-row offset (d4) is constant per thread. 8 consecutive threads
// share one (b,f) row -> coalesced gather lines; stores are linear.
__global__ void __launch_bounds__(TPB) fused_gather_se_kernel(
    const int* __restrict__ x,
    const float* __restrict__ tables,
    const float* __restrict__ w1,
    const float* __restrict__ w2,
    float* __restrict__ out) {

    __shared__ float s_sein[F];
    __shared__ float s_h[H];
    __shared__ float s_scale[F];

    const int t = threadIdx.x;

    // ---- SE-gate prologue: warp 0 only, redundant per block (L2-hot) ----
    if (t < 32) {
        if (t < F) {
            int idx = __ldg(&x[t * B + (B - 1)]);
            const float4* row = reinterpret_cast<const float4*>(
                tables + (size_t)t * ((size_t)V * D) + (size_t)idx * D);
            float s = 0.f;
            #pragma unroll
            for (int i = 0; i < D / 4; i++) {
                float4 v = __ldg(&row[i]);
                s += (v.x + v.y) + (v.z + v.w);
            }
            s_sein[t] = s * (1.0f / (float)D);
        }
        __syncwarp();
        if (t < H) {
            float acc = 0.f;
            #pragma unroll
            for (int f = 0; f < F; f++) acc += w1[t * F + f] * s_sein[f];
            s_h[t] = fmaxf(acc, 0.f);
        }
        __syncwarp();
        if (t < F) {
            float acc = 0.f;
            #pragma unroll
            for (int j = 0; j < H; j++) acc += w2[t * H + j] * s_h[j];
            s_scale[t] = 1.0f / (1.0f + __expf(-acc));
        }
    }
    __syncthreads();

    // ---- main gather-scale-store, 8 float4s per thread ----
    const int base = blockIdx.x * (TPB * ITEMS) + t;
    const int d4   = base & 7;          // constant across items (TPB % 8 == 0)
    const int r0   = base >> 3;         // row index of item 0; stride 32 rows/item

    // Batch the 8 index loads + src pointers + scales up front (x[] L2-resident)
    const float4* srcs[ITEMS];
    float sc[ITEMS];
    #pragma unroll
    for (int i = 0; i < ITEMS; i++) {
        int r = r0 + i * (TPB / 8);
        int f = r % F;
        int b = r / F;
        sc[i] = s_scale[f];
        int idx = __ldg(&x[f * B + b]);
        srcs[i] = reinterpret_cast<const float4*>(
            tables + (size_t)f * ((size_t)V * D) + (size_t)idx * D) + d4;
    }

    // Gather + scale + write-back store in groups of 4 (MLP>=4 in-flight gathers)
    #pragma unroll
    for (int g = 0; g < ITEMS / 4; g++) {
        float4 v[4];
        #pragma unroll
        for (int j = 0; j < 4; j++) {
            v[j] = __ldg(srcs[g * 4 + j]);
        }
        #pragma unroll
        for (int j = 0; j < 4; j++) {
            int i = g * 4 + j;
            v[j].x *= sc[i]; v[j].y *= sc[i]; v[j].z *= sc[i]; v[j].w *= sc[i];
            // plain write-back store: output lines stay dirty in L2 and are
            // re-written by the next graph replay -> steady-state DRAM writes ~0
            reinterpret_cast<float4*>(out)[base + i * TPB] = v[j];
        }
    }
}

extern "C" void kernel_launch(void* const* d_in, const int* in_sizes, int n_in,
                              void* d_out, int out_size) {
    const int*   x      = (const int*)d_in[0];
    const float* tables = (const float*)d_in[1];
    const float* w1     = (const float*)d_in[2];
    const float* w2     = (const float*)d_in[3];
    float*       out    = (float*)d_out;

    fused_gather_se_kernel<<<GRID, TPB>>>(x, tables, w1, w2, out);
}

// round 15
// speedup vs baseline: 1.2557x; 1.2557x over previous
#include <cuda_runtime.h>
#include <cuda_bf16.h>

// Problem constants
#define F 26
#define B 16384
#define V 100000
#define D 32
#define H 13

#define TPB   256
#define ITEMS 8
// total float4s = B*F*(D/4) = 3,407,872 = 1664 blocks * 256 threads * 8 items
#define GRID  1664

// Fused kernel (R5 winner config + ONE change: index loads and group-0 gathers
// are issued BEFORE __syncthreads, overlapping the SE-prologue's dependent
// load chain; BAR.SYNC does not drain in-flight LDGs).
//   prologue (warp 0): scale[f] = sigmoid(w2 @ relu(w1 @ mean_d(emb[f, x[f,B-1], :])))
//     (reference uses ONLY the last batch row for the gate: scale = gate[-1])
//   main: out[b, f*D+d] = tables[f][x[f,b]][d] * scale[f]
// One thread per 8 output float4s, item stride = TPB. Since TPB % 8 == 0, the
// float4-within-row offset (d4) is constant per thread. 8 consecutive threads
// share one (b,f) row -> coalesced gather lines; stores are linear.
__global__ void __launch_bounds__(TPB, 8) fused_gather_se_kernel(
    const int* __restrict__ x,
    const float* __restrict__ tables,
    const float* __restrict__ w1,
    const float* __restrict__ w2,
    float* __restrict__ out) {

    __shared__ float s_sein[F];
    __shared__ float s_h[H];
    __shared__ float s_scale[F];

    const int t = threadIdx.x;

    // ---- SE-gate prologue: warp 0 only, redundant per block (L2-hot) ----
    if (t < 32) {
        if (t < F) {
            int idx = __ldg(&x[t * B + (B - 1)]);
            const float4* row = reinterpret_cast<const float4*>(
                tables + (size_t)t * ((size_t)V * D) + (size_t)idx * D);
            float s = 0.f;
            #pragma unroll
            for (int i = 0; i < D / 4; i++) {
                float4 v = __ldg(&row[i]);
                s += (v.x + v.y) + (v.z + v.w);
            }
            s_sein[t] = s * (1.0f / (float)D);
        }
        __syncwarp();
        if (t < H) {
            float acc = 0.f;
            #pragma unroll
            for (int f = 0; f < F; f++) acc += w1[t * F + f] * s_sein[f];
            s_h[t] = fmaxf(acc, 0.f);
        }
        __syncwarp();
        if (t < F) {
            float acc = 0.f;
            #pragma unroll
            for (int j = 0; j < H; j++) acc += w2[t * H + j] * s_h[j];
            s_scale[t] = 1.0f / (1.0f + __expf(-acc));
        }
    }

    // ---- main setup: index loads + gather offsets (independent of prologue) ----
    const int base     = blockIdx.x * (TPB * ITEMS) + t;
    const unsigned dby = (unsigned)(base & 7) * 16u;  // byte offset of float4 in row
    const int r0       = base >> 3;                   // row of item 0; +32 rows/item

    unsigned off[ITEMS];   // 32-bit byte offsets into tables (span 333MB < 4GB)
    #pragma unroll
    for (int i = 0; i < ITEMS; i++) {
        int r = r0 + i * (TPB / 8);
        int f = r % F;
        int b = r / F;
        int idx = __ldg(&x[f * B + b]);
        off[i] = (unsigned)(f * V + idx) * (unsigned)(D * 4) + dby;
    }

    const char* tb = reinterpret_cast<const char*>(tables);
    float4* __restrict__ o4 = reinterpret_cast<float4*>(out);

    float4 v[4];

    // group-0 gathers issued BEFORE the barrier: in flight across BAR.SYNC,
    // overlapping warp 0's prologue latency
    #pragma unroll
    for (int j = 0; j < 4; j++)
        v[j] = __ldg(reinterpret_cast<const float4*>(tb + off[j]));

    __syncthreads();   // s_scale ready; group-0 gathers already in flight

    // group 0: scale + streaming store (output never re-read; keep tables in L2)
    #pragma unroll
    for (int j = 0; j < 4; j++) {
        float s = s_scale[(r0 + j * (TPB / 8)) % F];
        v[j].x *= s; v[j].y *= s; v[j].z *= s; v[j].w *= s;
        __stcs(&o4[base + j * TPB], v[j]);
    }

    // group 1
    #pragma unroll
    for (int j = 0; j < 4; j++)
        v[j] = __ldg(reinterpret_cast<const float4*>(tb + off[4 + j]));
    #pragma unroll
    for (int j = 0; j < 4; j++) {
        float s = s_scale[(r0 + (4 + j) * (TPB / 8)) % F];
        v[j].x *= s; v[j].y *= s; v[j].z *= s; v[j].w *= s;
        __stcs(&o4[base + (4 + j) * TPB], v[j]);
    }
}

extern "C" void kernel_launch(void* const* d_in, const int* in_sizes, int n_in,
                              void* d_out, int out_size) {
    const int*   x      = (const int*)d_in[0];
    const float* tables = (const float*)d_in[1];
    const float* w1     = (const float*)d_in[2];
    const float* w2     = (const float*)d_in[3];
    float*       out    = (float*)d_out;

    fused_gather_se_kernel<<<GRID, TPB>>>(x, tables, w1, w2, out);
}